// round 15
// baseline (speedup 1.0000x reference)
#include <cuda_runtime.h>
#include <cuda_fp16.h>
#include <cstdint>

// Problem constants
#define Cdim 2048
#define Sdim 2048
#define Bdim 4
#define Hdim 16
#define Ddim 128
#define Mtok (Bdim * Sdim)          // 8192
#define QKV_N (3 * Cdim)            // 6144

// ---------------------------------------------------------------------------
// Scratch (device globals — no allocation allowed)
// ---------------------------------------------------------------------------
__device__ __half g_qkvh[(size_t)Mtok * QKV_N];      // qkv (fp16)
__device__ __half g_xh[(size_t)Mtok * Cdim];         // x   (fp16)
__device__ __half g_yh[(size_t)Mtok * Cdim];         // y   (fp16)
__device__ __half g_wqkvT[(size_t)QKV_N * Cdim];     // [6144, 2048] (N,K) fp16
__device__ __half g_wprojT[(size_t)Cdim * Cdim];     // [2048, 2048] fp16

// ---------------------------------------------------------------------------
// PTX helpers (base-ISA only: cp.async / ldmatrix / mma.sync)
// ---------------------------------------------------------------------------
__device__ __forceinline__ uint32_t smem_u32(const void* p) {
    uint32_t a;
    asm("{ .reg .u64 t; cvta.to.shared.u64 t, %1; cvt.u32.u64 %0, t; }" : "=r"(a) : "l"(p));
    return a;
}

#define CP_ASYNC16(dst, src) \
    asm volatile("cp.async.cg.shared.global [%0], [%1], 16;" :: "r"(dst), "l"(src))
#define CP_COMMIT() asm volatile("cp.async.commit_group;" ::: "memory")
#define CP_WAIT(n)  asm volatile("cp.async.wait_group %0;" :: "n"(n) : "memory")

__device__ __forceinline__ void ldsm4(uint32_t* r, uint32_t addr) {
    asm volatile("ldmatrix.sync.aligned.m8n8.x4.shared.b16 {%0,%1,%2,%3}, [%4];"
                 : "=r"(r[0]), "=r"(r[1]), "=r"(r[2]), "=r"(r[3]) : "r"(addr));
}
__device__ __forceinline__ void ldsm4t(uint32_t* r, uint32_t addr) {
    asm volatile("ldmatrix.sync.aligned.m8n8.x4.trans.shared.b16 {%0,%1,%2,%3}, [%4];"
                 : "=r"(r[0]), "=r"(r[1]), "=r"(r[2]), "=r"(r[3]) : "r"(addr));
}

// fp16 MMA, fp32 accumulate
__device__ __forceinline__ void mma16816(float* d, const uint32_t* a,
                                         uint32_t b0, uint32_t b1) {
    asm volatile(
        "mma.sync.aligned.m16n8k16.row.col.f32.f16.f16.f32 "
        "{%0,%1,%2,%3}, {%4,%5,%6,%7}, {%8,%9}, {%0,%1,%2,%3};"
        : "+f"(d[0]), "+f"(d[1]), "+f"(d[2]), "+f"(d[3])
        : "r"(a[0]), "r"(a[1]), "r"(a[2]), "r"(a[3]), "r"(b0), "r"(b1));
}

// pack two fp32 -> fp16x2 (first arg in low half)
__device__ __forceinline__ uint32_t pack_f16(float lo, float hi) {
    uint32_t r;
    asm("cvt.rn.f16x2.f32 %0, %1, %2;" : "=r"(r) : "f"(hi), "f"(lo));
    return r;
}

// ---------------------------------------------------------------------------
// Conversion kernels (fp32 -> fp16) — vectorized (R14)
// ---------------------------------------------------------------------------
__global__ void convert_h_kernel(const float* __restrict__ in,
                                 __half* __restrict__ hi, int n)
{
    int i = (blockIdx.x * blockDim.x + threadIdx.x) * 8;
    if (i >= n) return;
    float4 a = *(const float4*)(in + i);
    float4 b = *(const float4*)(in + i + 4);
    uint4 o;
    o.x = pack_f16(a.x, a.y);
    o.y = pack_f16(a.z, a.w);
    o.z = pack_f16(b.x, b.y);
    o.w = pack_f16(b.z, b.w);
    *(uint4*)(hi + i) = o;
}

// W [K, N] fp32 -> Wt [N, K] fp16. Tile 32 (K) x 128 (N), 256 threads.
__global__ void transpose_h_kernel(const float* __restrict__ W,
                                   __half* __restrict__ Th, int K, int N)
{
    __shared__ float tile[32][129];
    const int n0 = blockIdx.x * 128, k0 = blockIdx.y * 32;
    const int t = threadIdx.x;   // 0..255

#pragma unroll
    for (int i = 0; i < 4; ++i) {
        int idx = t + i * 256;           // 0..1023
        int row = idx >> 5;              // k-row 0..31
        int col = (idx & 31) * 4;        // n-col 0..124
        float4 v = *(const float4*)(W + (size_t)(k0 + row) * N + n0 + col);
        tile[row][col + 0] = v.x;
        tile[row][col + 1] = v.y;
        tile[row][col + 2] = v.z;
        tile[row][col + 3] = v.w;
    }
    __syncthreads();

#pragma unroll
    for (int i = 0; i < 4; ++i) {
        int idx  = t + i * 256;          // 0..1023
        int nrow = idx >> 3;             // 0..127
        int kcol = (idx & 7) * 4;        // 0..28
        uint2 o;
        o.x = pack_f16(tile[kcol + 0][nrow], tile[kcol + 1][nrow]);
        o.y = pack_f16(tile[kcol + 2][nrow], tile[kcol + 3][nrow]);
        *(uint2*)(Th + (size_t)(n0 + nrow) * K + k0 + kcol) = o;
    }
}

// ---------------------------------------------------------------------------
// fp16 single-pass GEMM: C = A @ B^T + bias. CTA 128x128, BK=64, 8 warps
// (4m x 2n) 32x64 warp tiles, 3-stage cp.async, 2 CTAs/SM.
// ldsm addresses precomputed once; k16 stepped by XOR (k16<<5). Loop structure
// otherwise identical to the measured-best R11/R13 body.
// OUTM=0: fp32 C.  OUTM=1: fp16 Ch.
// ---------------------------------------------------------------------------
#define GA_TILE 16384                      // 128 x 64 fp16
#define GSTAGE (2 * GA_TILE)               // A, B = 32768
#define GEMM_SMEM (3 * GSTAGE)             // 98304

template<int OUTM>
__global__ __launch_bounds__(256, 2) void gemm_mma_kernel(
    const __half* __restrict__ Ah,
    const __half* __restrict__ Bh,
    const float* __restrict__ bias, float* __restrict__ C,
    __half* __restrict__ Ch,
    int M, int N, int K)
{
    extern __shared__ char smem[];
    const uint32_t sbase = smem_u32(smem);

    const int t   = threadIdx.x;
    const int wid = t >> 5;
    const int lid = t & 31;
    const int n0  = blockIdx.x * 128;
    const int m0  = blockIdx.y * 128;
    const int wm  = (wid & 3) * 32;
    const int wn  = (wid >> 2) * 64;

    const __half* gA = Ah + (size_t)m0 * K;
    const __half* gB = Bh + (size_t)n0 * K;

    float acc[2][8][4];
#pragma unroll
    for (int mt = 0; mt < 2; ++mt)
#pragma unroll
        for (int nt = 0; nt < 8; ++nt)
#pragma unroll
            for (int e = 0; e < 4; ++e) acc[mt][nt][e] = 0.f;

    // Rows are 128B (64 fp16); swizzle: j ^ (row & 7) on 16B groups.
    auto load_stage = [&](int stage, int k0) {
        uint32_t sb = sbase + stage * GSTAGE;
#pragma unroll
        for (int i = 0; i < 4; ++i) {
            int idx = t + i * 256;          // < 1024
            int row = idx >> 3, j = idx & 7;
            uint32_t dst = sb + row * 128 + ((j ^ (row & 7)) << 4);
            CP_ASYNC16(dst, gA + (size_t)row * K + k0 + j * 8);
            CP_ASYNC16(dst + GA_TILE, gB + (size_t)row * K + k0 + j * 8);
        }
    };

    // Precompute stage-relative ldsm offsets at k16=0 (jg = lk).
    // Step k16 by XOR (k16<<5): jg = lk + 2*k16; bits disjoint from lk and
    // from the (row&7) XOR field => (jg^(row&7))<<4 == base ^ (k16<<5).
    const int lrow8 = (lid & 7) + ((lid >> 3) & 1) * 8;
    const int lk    = (lid >> 4) & 1;
    uint32_t aoff0[2], boff0[4];
#pragma unroll
    for (int mt = 0; mt < 2; ++mt) {
        int r = wm + mt * 16 + lrow8;
        aoff0[mt] = r * 128 + ((lk ^ (r & 7)) << 4);
    }
#pragma unroll
    for (int nb = 0; nb < 4; ++nb) {
        int r = wn + nb * 16 + lrow8;
        boff0[nb] = GA_TILE + r * 128 + ((lk ^ (r & 7)) << 4);
    }

    const int nk = K / 64;                  // 32 chunks
    load_stage(0, 0);  CP_COMMIT();
    load_stage(1, 64); CP_COMMIT();

    for (int c = 0; c < nk; ++c) {
        CP_WAIT(1);
        __syncthreads();
        if (c + 2 < nk) load_stage((c + 2) % 3, (c + 2) * 64);
        CP_COMMIT();

        const uint32_t sb = sbase + (c % 3) * GSTAGE;

#pragma unroll
        for (int k16 = 0; k16 < 4; ++k16) {
            const uint32_t x = (uint32_t)k16 << 5;

            uint32_t bh[16];
#pragma unroll
            for (int nb = 0; nb < 4; ++nb)
                ldsm4(&bh[nb * 4], (sb + boff0[nb]) ^ x);
#pragma unroll
            for (int mt = 0; mt < 2; ++mt) {
                uint32_t ah[4];
                ldsm4(ah, (sb + aoff0[mt]) ^ x);
#pragma unroll
                for (int nb = 0; nb < 4; ++nb) {
                    mma16816(acc[mt][2 * nb],     ah, bh[nb * 4 + 0], bh[nb * 4 + 2]);
                    mma16816(acc[mt][2 * nb + 1], ah, bh[nb * 4 + 1], bh[nb * 4 + 3]);
                }
            }
        }
    }

    const int gid = lid >> 2;
    const int tig = lid & 3;
#pragma unroll
    for (int mt = 0; mt < 2; ++mt) {
        int m = m0 + wm + mt * 16 + gid;
#pragma unroll
        for (int nt = 0; nt < 8; ++nt) {
            int n = n0 + wn + nt * 8 + tig * 2;
            float b0 = bias[n], b1 = bias[n + 1];
            float v00 = acc[mt][nt][0] + b0, v01 = acc[mt][nt][1] + b1;
            float v10 = acc[mt][nt][2] + b0, v11 = acc[mt][nt][3] + b1;
            if (OUTM == 0) {
                *(float2*)(C + (size_t)m * N + n)       = make_float2(v00, v01);
                *(float2*)(C + (size_t)(m + 8) * N + n) = make_float2(v10, v11);
            } else {
                *(uint32_t*)(Ch + (size_t)m * N + n)       = pack_f16(v00, v01);
                *(uint32_t*)(Ch + (size_t)(m + 8) * N + n) = pack_f16(v10, v11);
            }
        }
    }
}

// ---------------------------------------------------------------------------
// Flash attention, pure fp16 MMA operands, causal. (R13 config — unchanged)
// CTA: 128 q-rows x 64-kv chunks. 8 warps x 16 q-rows. 2-stage KV, 2 CTAs/SM.
// LPT scheduling: heaviest q-tiles (largest qt) launch first.
// ---------------------------------------------------------------------------
#define KV_TILE_B 16384                     // 64 rows x 256 B
#define KV_STAGE_B (2 * KV_TILE_B)          // K, V
#define Q_TILE_B   32768                    // 128 rows x 256 B
#define ATTN_SMEM (Q_TILE_B + 2 * KV_STAGE_B)   // 98304

__global__ __launch_bounds__(256, 2) void attn_mma_kernel()
{
    extern __shared__ char sm8[];
    const uint32_t sb  = smem_u32(sm8);
    const uint32_t sQh = sb;
    const uint32_t sKV = sb + Q_TILE_B;

    const int t   = threadIdx.x;
    const int wid = t >> 5;
    const int lid = t & 31;
    const int qt  = (Sdim / 128 - 1) - blockIdx.x;   // LPT: heavy tiles first
    const int h   = blockIdx.y;
    const int b   = blockIdx.z;
    const int m0  = qt * 128;
    const int wm  = wid * 16;
    const int gid = lid >> 2;
    const int tig = lid & 3;
    const int lrow8 = (lid & 7) + ((lid >> 3) & 1) * 8;
    const int lk    = (lid >> 4) & 1;

    const size_t tok0 = ((size_t)b * Sdim + m0) * QKV_N;
    const __half* qh = g_qkvh + tok0 + h * Ddim;
    const size_t kvtok = (size_t)b * Sdim * QKV_N;
    const __half* kv_base[2] = {
        g_qkvh + kvtok + Cdim + h * Ddim,      // K
        g_qkvh + kvtok + 2 * Cdim + h * Ddim   // V
    };

    auto load_kv = [&](int stage, int n0) {
        uint32_t dstb = sKV + stage * KV_STAGE_B;
#pragma unroll
        for (int i = 0; i < 8; ++i) {
            int idx  = t + i * 256;            // 0..2047
            int tile = idx >> 10;
            int rem  = idx & 1023;
            int row  = rem >> 4, j = rem & 15;
            const void* src = kv_base[tile] + (size_t)(n0 + row) * QKV_N + j * 8;
            uint32_t dst = dstb + tile * KV_TILE_B + row * 256 + ((j ^ (row & 7)) << 4);
            CP_ASYNC16(dst, src);
        }
    };

    const int ktmax = (m0 >> 6) + 1;

    // Q tile loads (group 0, with kv chunk 0)
#pragma unroll
    for (int i = 0; i < 8; ++i) {
        int idx  = t + i * 256;                // 0..2047
        int row  = idx >> 4, j = idx & 15;
        const __half* src = qh + (size_t)row * QKV_N + j * 8;
        uint32_t dst = sQh + row * 256 + ((j ^ (row & 7)) << 4);
        CP_ASYNC16(dst, src);
    }
    load_kv(0, 0);
    CP_COMMIT();                               // g0: Q + kv0
    if (ktmax >= 1) load_kv(1, 64);
    CP_COMMIT();

    float o[16][4];
    float m_i[2] = {-1e30f, -1e30f};
    float l_i[2] = {0.f, 0.f};
#pragma unroll
    for (int nt = 0; nt < 16; ++nt)
#pragma unroll
        for (int e = 0; e < 4; ++e) o[nt][e] = 0.f;

    const float scale = 0.08838834764831845f;   // 1/sqrt(128)
    const int r0g = m0 + wm + gid;

    for (int kt = 0; kt <= ktmax; ++kt) {
        const int n0 = kt << 6;
        CP_WAIT(1);
        __syncthreads();

        const uint32_t st  = sKV + (kt & 1) * KV_STAGE_B;
        const uint32_t sKh = st, sVh = st + KV_TILE_B;

        if (m0 + wm + 15 >= n0) {
            // ---- S = Q K^T ----
            float s[8][4];
#pragma unroll
            for (int nt = 0; nt < 8; ++nt)
#pragma unroll
                for (int e = 0; e < 4; ++e) s[nt][e] = 0.f;

#pragma unroll
            for (int ks = 0; ks < 8; ++ks) {
                const int jg = ks * 2 + lk;
                const int arow = wm + lrow8;
                uint32_t aoff = arow * 256 + ((jg ^ (arow & 7)) << 4);
                uint32_t qf[4];
                ldsm4(qf, sQh + aoff);
#pragma unroll
                for (int g = 0; g < 4; ++g) {
                    const int brow = g * 16 + lrow8;
                    uint32_t boff = brow * 256 + ((jg ^ (brow & 7)) << 4);
                    uint32_t kh[4];
                    ldsm4(kh, sKh + boff);
                    mma16816(s[2 * g],     qf, kh[0], kh[2]);
                    mma16816(s[2 * g + 1], qf, kh[1], kh[3]);
                }
            }

            // scale + causal mask
            const bool diag = (n0 + 63 > m0 + wm);
#pragma unroll
            for (int nt = 0; nt < 8; ++nt) {
                const int c0 = n0 + nt * 8 + tig * 2;
#pragma unroll
                for (int e = 0; e < 4; ++e) s[nt][e] *= scale;
                if (diag) {
                    if (c0     > r0g)     s[nt][0] = -1e30f;
                    if (c0 + 1 > r0g)     s[nt][1] = -1e30f;
                    if (c0     > r0g + 8) s[nt][2] = -1e30f;
                    if (c0 + 1 > r0g + 8) s[nt][3] = -1e30f;
                }
            }

            // ---- online softmax ----
#pragma unroll
            for (int rr = 0; rr < 2; ++rr) {
                float mx = -1e30f;
#pragma unroll
                for (int nt = 0; nt < 8; ++nt)
                    mx = fmaxf(mx, fmaxf(s[nt][2 * rr], s[nt][2 * rr + 1]));
                mx = fmaxf(mx, __shfl_xor_sync(0xffffffffu, mx, 1));
                mx = fmaxf(mx, __shfl_xor_sync(0xffffffffu, mx, 2));
                float m_new = fmaxf(m_i[rr], mx);
                float alpha = __expf(m_i[rr] - m_new);
                float sum = 0.f;
#pragma unroll
                for (int nt = 0; nt < 8; ++nt) {
                    float p0 = __expf(s[nt][2 * rr]     - m_new);
                    float p1 = __expf(s[nt][2 * rr + 1] - m_new);
                    s[nt][2 * rr]     = p0;
                    s[nt][2 * rr + 1] = p1;
                    sum += p0 + p1;
                }
                sum += __shfl_xor_sync(0xffffffffu, sum, 1);
                sum += __shfl_xor_sync(0xffffffffu, sum, 2);
                l_i[rr] = l_i[rr] * alpha + sum;
                m_i[rr] = m_new;
#pragma unroll
                for (int nt = 0; nt < 16; ++nt) {
                    o[nt][2 * rr]     *= alpha;
                    o[nt][2 * rr + 1] *= alpha;
                }
            }

            // ---- O += P V ----
#pragma unroll
            for (int j = 0; j < 4; ++j) {
                uint32_t ap[4];
#pragma unroll
                for (int half = 0; half < 2; ++half) {
                    const float* sp = s[2 * j + half];
                    ap[half * 2 + 0] = pack_f16(sp[0], sp[1]);
                    ap[half * 2 + 1] = pack_f16(sp[2], sp[3]);
                }
                const int vrow = j * 16 + lrow8;
#pragma unroll
                for (int g = 0; g < 8; ++g) {
                    const int jj = g * 2 + lk;
                    uint32_t voff = vrow * 256 + ((jj ^ (vrow & 7)) << 4);
                    uint32_t vh[4];
                    ldsm4t(vh, sVh + voff);
                    mma16816(o[2 * g],     ap, vh[0], vh[1]);
                    mma16816(o[2 * g + 1], ap, vh[2], vh[3]);
                }
            }
        }

        __syncthreads();
        if (kt + 2 <= ktmax) load_kv(kt & 1, (kt + 2) << 6);
        CP_COMMIT();
    }

    // ---- epilogue: normalize, write fp16 y ----
    const float inv0 = 1.0f / l_i[0];
    const float inv1 = 1.0f / l_i[1];
    const size_t ybase = (size_t)b * Sdim * Cdim + (size_t)h * Ddim;
    __half* yh = g_yh + ybase;
    const size_t row0 = (size_t)(m0 + wm + gid) * Cdim;
    const size_t row1 = row0 + 8 * Cdim;
#pragma unroll
    for (int nt = 0; nt < 16; ++nt) {
        const int col = nt * 8 + tig * 2;
        *(uint32_t*)(yh + row0 + col) = pack_f16(o[nt][0] * inv0, o[nt][1] * inv0);
        *(uint32_t*)(yh + row1 + col) = pack_f16(o[nt][2] * inv1, o[nt][3] * inv1);
    }
}

// ---------------------------------------------------------------------------
// Launch
// ---------------------------------------------------------------------------
extern "C" void kernel_launch(void* const* d_in, const int* in_sizes, int n_in,
                              void* d_out, int out_size)
{
    const float* x      = (const float*)d_in[0];
    const float* w_qkv  = (const float*)d_in[1];
    const float* b_qkv  = (const float*)d_in[2];
    const float* w_proj = (const float*)d_in[3];
    const float* b_proj = (const float*)d_in[4];
    float* out = (float*)d_out;

    __half *qkvh, *xh, *yh, *wq, *wp;
    cudaGetSymbolAddress((void**)&qkvh, g_qkvh);
    cudaGetSymbolAddress((void**)&xh,  g_xh);
    cudaGetSymbolAddress((void**)&yh,  g_yh);
    cudaGetSymbolAddress((void**)&wq,  g_wqkvT);
    cudaGetSymbolAddress((void**)&wp,  g_wprojT);

    cudaFuncSetAttribute(gemm_mma_kernel<0>,
                         cudaFuncAttributeMaxDynamicSharedMemorySize, GEMM_SMEM);
    cudaFuncSetAttribute(gemm_mma_kernel<1>,
                         cudaFuncAttributeMaxDynamicSharedMemorySize, GEMM_SMEM);
    cudaFuncSetAttribute(attn_mma_kernel,
                         cudaFuncAttributeMaxDynamicSharedMemorySize, ATTN_SMEM);

    // 1) input convert / weight transposes (fp16, vectorized)
    {
        int n = Mtok * Cdim;
        convert_h_kernel<<<n / 8 / 256, 256>>>(x, xh, n);
    }
    transpose_h_kernel<<<dim3(QKV_N / 128, Cdim / 32), 256>>>(
        w_qkv, wq, Cdim, QKV_N);
    transpose_h_kernel<<<dim3(Cdim / 128, Cdim / 32), 256>>>(
        w_proj, wp, Cdim, Cdim);

    // 2) qkv = x @ w_qkv + b_qkv   [8192, 6144] -> fp16
    gemm_mma_kernel<1><<<dim3(QKV_N / 128, Mtok / 128), 256, GEMM_SMEM>>>(
        xh, wq, b_qkv, nullptr, qkvh, Mtok, QKV_N, Cdim);

    // 3) flash attention (fp16) -> yh  (LPT block order)
    {
        dim3 grid(Sdim / 128, Hdim, Bdim);
        attn_mma_kernel<<<grid, 256, ATTN_SMEM>>>();
    }

    // 4) out = y @ w_proj + b_proj   [8192, 2048] fp32
    gemm_mma_kernel<0><<<dim3(Cdim / 128, Mtok / 128), 256, GEMM_SMEM>>>(
        yh, wp, b_proj, out, nullptr, Mtok, Cdim, Cdim);
}

// round 16
// speedup vs baseline: 1.0067x; 1.0067x over previous
#include <cuda_runtime.h>
#include <cuda_fp16.h>
#include <cstdint>

// Problem constants
#define Cdim 2048
#define Sdim 2048
#define Bdim 4
#define Hdim 16
#define Ddim 128
#define Mtok (Bdim * Sdim)          // 8192
#define QKV_N (3 * Cdim)            // 6144

// ---------------------------------------------------------------------------
// Scratch (device globals — no allocation allowed)
// ---------------------------------------------------------------------------
__device__ __half g_qkvh[(size_t)Mtok * QKV_N];      // qkv (fp16)
__device__ __half g_xh[(size_t)Mtok * Cdim];         // x   (fp16)
__device__ __half g_yh[(size_t)Mtok * Cdim];         // y   (fp16)
__device__ __half g_wqkvT[(size_t)QKV_N * Cdim];     // [6144, 2048] (N,K) fp16
__device__ __half g_wprojT[(size_t)Cdim * Cdim];     // [2048, 2048] fp16

// ---------------------------------------------------------------------------
// PTX helpers (base-ISA only: cp.async / ldmatrix / mma.sync)
// ---------------------------------------------------------------------------
__device__ __forceinline__ uint32_t smem_u32(const void* p) {
    uint32_t a;
    asm("{ .reg .u64 t; cvta.to.shared.u64 t, %1; cvt.u32.u64 %0, t; }" : "=r"(a) : "l"(p));
    return a;
}

#define CP_ASYNC16(dst, src) \
    asm volatile("cp.async.cg.shared.global [%0], [%1], 16;" :: "r"(dst), "l"(src))
#define CP_COMMIT() asm volatile("cp.async.commit_group;" ::: "memory")
#define CP_WAIT(n)  asm volatile("cp.async.wait_group %0;" :: "n"(n) : "memory")

__device__ __forceinline__ void ldsm4(uint32_t* r, uint32_t addr) {
    asm volatile("ldmatrix.sync.aligned.m8n8.x4.shared.b16 {%0,%1,%2,%3}, [%4];"
                 : "=r"(r[0]), "=r"(r[1]), "=r"(r[2]), "=r"(r[3]) : "r"(addr));
}
__device__ __forceinline__ void ldsm4t(uint32_t* r, uint32_t addr) {
    asm volatile("ldmatrix.sync.aligned.m8n8.x4.trans.shared.b16 {%0,%1,%2,%3}, [%4];"
                 : "=r"(r[0]), "=r"(r[1]), "=r"(r[2]), "=r"(r[3]) : "r"(addr));
}

// fp16 MMA, fp32 accumulate
__device__ __forceinline__ void mma16816(float* d, const uint32_t* a,
                                         uint32_t b0, uint32_t b1) {
    asm volatile(
        "mma.sync.aligned.m16n8k16.row.col.f32.f16.f16.f32 "
        "{%0,%1,%2,%3}, {%4,%5,%6,%7}, {%8,%9}, {%0,%1,%2,%3};"
        : "+f"(d[0]), "+f"(d[1]), "+f"(d[2]), "+f"(d[3])
        : "r"(a[0]), "r"(a[1]), "r"(a[2]), "r"(a[3]), "r"(b0), "r"(b1));
}

// pack two fp32 -> fp16x2 (first arg in low half)
__device__ __forceinline__ uint32_t pack_f16(float lo, float hi) {
    uint32_t r;
    asm("cvt.rn.f16x2.f32 %0, %1, %2;" : "=r"(r) : "f"(hi), "f"(lo));
    return r;
}

// ---------------------------------------------------------------------------
// Fused prologue: x convert + both weight transposes in ONE launch.
// Block partition:
//   [0, NB_CONV)             : convert x (8 fp32 -> 8 fp16 per thread)
//   [NB_CONV, +NB_TQ)        : transpose w_qkv  (tile 32K x 128N)
//   [NB_CONV+NB_TQ, +NB_TP)  : transpose w_proj
// All paths use the same rounding instructions as R15 -> bitwise-identical.
// ---------------------------------------------------------------------------
#define NB_CONV (Mtok * Cdim / 8 / 256)          // 8192
#define NB_TQ   ((QKV_N / 128) * (Cdim / 32))    // 48*64 = 3072
#define NB_TP   ((Cdim / 128) * (Cdim / 32))     // 16*64 = 1024
#define NB_PRO  (NB_CONV + NB_TQ + NB_TP)        // 12288

__device__ __forceinline__ void transpose_tile(const float* __restrict__ W,
                                               __half* __restrict__ Th,
                                               int K, int N, int bx, int by,
                                               float (*tile)[129])
{
    const int n0 = bx * 128, k0 = by * 32;
    const int t = threadIdx.x;   // 0..255

#pragma unroll
    for (int i = 0; i < 4; ++i) {
        int idx = t + i * 256;           // 0..1023
        int row = idx >> 5;              // k-row 0..31
        int col = (idx & 31) * 4;        // n-col 0..124
        float4 v = *(const float4*)(W + (size_t)(k0 + row) * N + n0 + col);
        tile[row][col + 0] = v.x;
        tile[row][col + 1] = v.y;
        tile[row][col + 2] = v.z;
        tile[row][col + 3] = v.w;
    }
    __syncthreads();

#pragma unroll
    for (int i = 0; i < 4; ++i) {
        int idx  = t + i * 256;          // 0..1023
        int nrow = idx >> 3;             // 0..127
        int kcol = (idx & 7) * 4;        // 0..28
        uint2 o;
        o.x = pack_f16(tile[kcol + 0][nrow], tile[kcol + 1][nrow]);
        o.y = pack_f16(tile[kcol + 2][nrow], tile[kcol + 3][nrow]);
        *(uint2*)(Th + (size_t)(n0 + nrow) * K + k0 + kcol) = o;
    }
}

__global__ __launch_bounds__(256) void prologue_kernel(
    const float* __restrict__ x,      __half* __restrict__ xh,
    const float* __restrict__ w_qkv,  __half* __restrict__ wqT,
    const float* __restrict__ w_proj, __half* __restrict__ wpT)
{
    __shared__ float tile[32][129];
    const int bid = blockIdx.x;

    if (bid < NB_CONV) {
        // x convert: 8 elements/thread
        int i = (bid * 256 + threadIdx.x) * 8;
        float4 a = *(const float4*)(x + i);
        float4 b = *(const float4*)(x + i + 4);
        uint4 o;
        o.x = pack_f16(a.x, a.y);
        o.y = pack_f16(a.z, a.w);
        o.z = pack_f16(b.x, b.y);
        o.w = pack_f16(b.z, b.w);
        *(uint4*)(xh + i) = o;
    } else if (bid < NB_CONV + NB_TQ) {
        int tb = bid - NB_CONV;
        transpose_tile(w_qkv, wqT, Cdim, QKV_N, tb % (QKV_N / 128), tb / (QKV_N / 128), tile);
    } else {
        int tb = bid - NB_CONV - NB_TQ;
        transpose_tile(w_proj, wpT, Cdim, Cdim, tb % (Cdim / 128), tb / (Cdim / 128), tile);
    }
}

// ---------------------------------------------------------------------------
// fp16 single-pass GEMM (R15 body — best measured): C = A @ B^T + bias.
// CTA 128x128, BK=64, 8 warps (4m x 2n) 32x64 warp tiles, 3-stage cp.async,
// 2 CTAs/SM. ldsm addresses precomputed; k16 stepped by XOR (k16<<5).
// OUTM=0: fp32 C.  OUTM=1: fp16 Ch.
// ---------------------------------------------------------------------------
#define GA_TILE 16384                      // 128 x 64 fp16
#define GSTAGE (2 * GA_TILE)               // A, B = 32768
#define GEMM_SMEM (3 * GSTAGE)             // 98304

template<int OUTM>
__global__ __launch_bounds__(256, 2) void gemm_mma_kernel(
    const __half* __restrict__ Ah,
    const __half* __restrict__ Bh,
    const float* __restrict__ bias, float* __restrict__ C,
    __half* __restrict__ Ch,
    int M, int N, int K)
{
    extern __shared__ char smem[];
    const uint32_t sbase = smem_u32(smem);

    const int t   = threadIdx.x;
    const int wid = t >> 5;
    const int lid = t & 31;
    const int n0  = blockIdx.x * 128;
    const int m0  = blockIdx.y * 128;
    const int wm  = (wid & 3) * 32;
    const int wn  = (wid >> 2) * 64;

    const __half* gA = Ah + (size_t)m0 * K;
    const __half* gB = Bh + (size_t)n0 * K;

    float acc[2][8][4];
#pragma unroll
    for (int mt = 0; mt < 2; ++mt)
#pragma unroll
        for (int nt = 0; nt < 8; ++nt)
#pragma unroll
            for (int e = 0; e < 4; ++e) acc[mt][nt][e] = 0.f;

    auto load_stage = [&](int stage, int k0) {
        uint32_t sb = sbase + stage * GSTAGE;
#pragma unroll
        for (int i = 0; i < 4; ++i) {
            int idx = t + i * 256;          // < 1024
            int row = idx >> 3, j = idx & 7;
            uint32_t dst = sb + row * 128 + ((j ^ (row & 7)) << 4);
            CP_ASYNC16(dst, gA + (size_t)row * K + k0 + j * 8);
            CP_ASYNC16(dst + GA_TILE, gB + (size_t)row * K + k0 + j * 8);
        }
    };

    const int lrow8 = (lid & 7) + ((lid >> 3) & 1) * 8;
    const int lk    = (lid >> 4) & 1;
    uint32_t aoff0[2], boff0[4];
#pragma unroll
    for (int mt = 0; mt < 2; ++mt) {
        int r = wm + mt * 16 + lrow8;
        aoff0[mt] = r * 128 + ((lk ^ (r & 7)) << 4);
    }
#pragma unroll
    for (int nb = 0; nb < 4; ++nb) {
        int r = wn + nb * 16 + lrow8;
        boff0[nb] = GA_TILE + r * 128 + ((lk ^ (r & 7)) << 4);
    }

    const int nk = K / 64;                  // 32 chunks
    load_stage(0, 0);  CP_COMMIT();
    load_stage(1, 64); CP_COMMIT();

    for (int c = 0; c < nk; ++c) {
        CP_WAIT(1);
        __syncthreads();
        if (c + 2 < nk) load_stage((c + 2) % 3, (c + 2) * 64);
        CP_COMMIT();

        const uint32_t sb = sbase + (c % 3) * GSTAGE;

#pragma unroll
        for (int k16 = 0; k16 < 4; ++k16) {
            const uint32_t x = (uint32_t)k16 << 5;

            uint32_t bh[16];
#pragma unroll
            for (int nb = 0; nb < 4; ++nb)
                ldsm4(&bh[nb * 4], (sb + boff0[nb]) ^ x);
#pragma unroll
            for (int mt = 0; mt < 2; ++mt) {
                uint32_t ah[4];
                ldsm4(ah, (sb + aoff0[mt]) ^ x);
#pragma unroll
                for (int nb = 0; nb < 4; ++nb) {
                    mma16816(acc[mt][2 * nb],     ah, bh[nb * 4 + 0], bh[nb * 4 + 2]);
                    mma16816(acc[mt][2 * nb + 1], ah, bh[nb * 4 + 1], bh[nb * 4 + 3]);
                }
            }
        }
    }

    const int gid = lid >> 2;
    const int tig = lid & 3;
#pragma unroll
    for (int mt = 0; mt < 2; ++mt) {
        int m = m0 + wm + mt * 16 + gid;
#pragma unroll
        for (int nt = 0; nt < 8; ++nt) {
            int n = n0 + wn + nt * 8 + tig * 2;
            float b0 = bias[n], b1 = bias[n + 1];
            float v00 = acc[mt][nt][0] + b0, v01 = acc[mt][nt][1] + b1;
            float v10 = acc[mt][nt][2] + b0, v11 = acc[mt][nt][3] + b1;
            if (OUTM == 0) {
                *(float2*)(C + (size_t)m * N + n)       = make_float2(v00, v01);
                *(float2*)(C + (size_t)(m + 8) * N + n) = make_float2(v10, v11);
            } else {
                *(uint32_t*)(Ch + (size_t)m * N + n)       = pack_f16(v00, v01);
                *(uint32_t*)(Ch + (size_t)(m + 8) * N + n) = pack_f16(v10, v11);
            }
        }
    }
}

// ---------------------------------------------------------------------------
// Flash attention, pure fp16 MMA operands, causal. (R13 config — unchanged)
// CTA: 128 q-rows x 64-kv chunks. 8 warps x 16 q-rows. 2-stage KV, 2 CTAs/SM.
// LPT scheduling: heaviest q-tiles (largest qt) launch first.
// ---------------------------------------------------------------------------
#define KV_TILE_B 16384                     // 64 rows x 256 B
#define KV_STAGE_B (2 * KV_TILE_B)          // K, V
#define Q_TILE_B   32768                    // 128 rows x 256 B
#define ATTN_SMEM (Q_TILE_B + 2 * KV_STAGE_B)   // 98304

__global__ __launch_bounds__(256, 2) void attn_mma_kernel()
{
    extern __shared__ char sm8[];
    const uint32_t sb  = smem_u32(sm8);
    const uint32_t sQh = sb;
    const uint32_t sKV = sb + Q_TILE_B;

    const int t   = threadIdx.x;
    const int wid = t >> 5;
    const int lid = t & 31;
    const int qt  = (Sdim / 128 - 1) - blockIdx.x;   // LPT: heavy tiles first
    const int h   = blockIdx.y;
    const int b   = blockIdx.z;
    const int m0  = qt * 128;
    const int wm  = wid * 16;
    const int gid = lid >> 2;
    const int tig = lid & 3;
    const int lrow8 = (lid & 7) + ((lid >> 3) & 1) * 8;
    const int lk    = (lid >> 4) & 1;

    const size_t tok0 = ((size_t)b * Sdim + m0) * QKV_N;
    const __half* qh = g_qkvh + tok0 + h * Ddim;
    const size_t kvtok = (size_t)b * Sdim * QKV_N;
    const __half* kv_base[2] = {
        g_qkvh + kvtok + Cdim + h * Ddim,      // K
        g_qkvh + kvtok + 2 * Cdim + h * Ddim   // V
    };

    auto load_kv = [&](int stage, int n0) {
        uint32_t dstb = sKV + stage * KV_STAGE_B;
#pragma unroll
        for (int i = 0; i < 8; ++i) {
            int idx  = t + i * 256;            // 0..2047
            int tile = idx >> 10;
            int rem  = idx & 1023;
            int row  = rem >> 4, j = rem & 15;
            const void* src = kv_base[tile] + (size_t)(n0 + row) * QKV_N + j * 8;
            uint32_t dst = dstb + tile * KV_TILE_B + row * 256 + ((j ^ (row & 7)) << 4);
            CP_ASYNC16(dst, src);
        }
    };

    const int ktmax = (m0 >> 6) + 1;

#pragma unroll
    for (int i = 0; i < 8; ++i) {
        int idx  = t + i * 256;                // 0..2047
        int row  = idx >> 4, j = idx & 15;
        const __half* src = qh + (size_t)row * QKV_N + j * 8;
        uint32_t dst = sQh + row * 256 + ((j ^ (row & 7)) << 4);
        CP_ASYNC16(dst, src);
    }
    load_kv(0, 0);
    CP_COMMIT();                               // g0: Q + kv0
    if (ktmax >= 1) load_kv(1, 64);
    CP_COMMIT();

    float o[16][4];
    float m_i[2] = {-1e30f, -1e30f};
    float l_i[2] = {0.f, 0.f};
#pragma unroll
    for (int nt = 0; nt < 16; ++nt)
#pragma unroll
        for (int e = 0; e < 4; ++e) o[nt][e] = 0.f;

    const float scale = 0.08838834764831845f;   // 1/sqrt(128)
    const int r0g = m0 + wm + gid;

    for (int kt = 0; kt <= ktmax; ++kt) {
        const int n0 = kt << 6;
        CP_WAIT(1);
        __syncthreads();

        const uint32_t st  = sKV + (kt & 1) * KV_STAGE_B;
        const uint32_t sKh = st, sVh = st + KV_TILE_B;

        if (m0 + wm + 15 >= n0) {
            // ---- S = Q K^T ----
            float s[8][4];
#pragma unroll
            for (int nt = 0; nt < 8; ++nt)
#pragma unroll
                for (int e = 0; e < 4; ++e) s[nt][e] = 0.f;

#pragma unroll
            for (int ks = 0; ks < 8; ++ks) {
                const int jg = ks * 2 + lk;
                const int arow = wm + lrow8;
                uint32_t aoff = arow * 256 + ((jg ^ (arow & 7)) << 4);
                uint32_t qf[4];
                ldsm4(qf, sQh + aoff);
#pragma unroll
                for (int g = 0; g < 4; ++g) {
                    const int brow = g * 16 + lrow8;
                    uint32_t boff = brow * 256 + ((jg ^ (brow & 7)) << 4);
                    uint32_t kh[4];
                    ldsm4(kh, sKh + boff);
                    mma16816(s[2 * g],     qf, kh[0], kh[2]);
                    mma16816(s[2 * g + 1], qf, kh[1], kh[3]);
                }
            }

            const bool diag = (n0 + 63 > m0 + wm);
#pragma unroll
            for (int nt = 0; nt < 8; ++nt) {
                const int c0 = n0 + nt * 8 + tig * 2;
#pragma unroll
                for (int e = 0; e < 4; ++e) s[nt][e] *= scale;
                if (diag) {
                    if (c0     > r0g)     s[nt][0] = -1e30f;
                    if (c0 + 1 > r0g)     s[nt][1] = -1e30f;
                    if (c0     > r0g + 8) s[nt][2] = -1e30f;
                    if (c0 + 1 > r0g + 8) s[nt][3] = -1e30f;
                }
            }

#pragma unroll
            for (int rr = 0; rr < 2; ++rr) {
                float mx = -1e30f;
#pragma unroll
                for (int nt = 0; nt < 8; ++nt)
                    mx = fmaxf(mx, fmaxf(s[nt][2 * rr], s[nt][2 * rr + 1]));
                mx = fmaxf(mx, __shfl_xor_sync(0xffffffffu, mx, 1));
                mx = fmaxf(mx, __shfl_xor_sync(0xffffffffu, mx, 2));
                float m_new = fmaxf(m_i[rr], mx);
                float alpha = __expf(m_i[rr] - m_new);
                float sum = 0.f;
#pragma unroll
                for (int nt = 0; nt < 8; ++nt) {
                    float p0 = __expf(s[nt][2 * rr]     - m_new);
                    float p1 = __expf(s[nt][2 * rr + 1] - m_new);
                    s[nt][2 * rr]     = p0;
                    s[nt][2 * rr + 1] = p1;
                    sum += p0 + p1;
                }
                sum += __shfl_xor_sync(0xffffffffu, sum, 1);
                sum += __shfl_xor_sync(0xffffffffu, sum, 2);
                l_i[rr] = l_i[rr] * alpha + sum;
                m_i[rr] = m_new;
#pragma unroll
                for (int nt = 0; nt < 16; ++nt) {
                    o[nt][2 * rr]     *= alpha;
                    o[nt][2 * rr + 1] *= alpha;
                }
            }

#pragma unroll
            for (int j = 0; j < 4; ++j) {
                uint32_t ap[4];
#pragma unroll
                for (int half = 0; half < 2; ++half) {
                    const float* sp = s[2 * j + half];
                    ap[half * 2 + 0] = pack_f16(sp[0], sp[1]);
                    ap[half * 2 + 1] = pack_f16(sp[2], sp[3]);
                }
                const int vrow = j * 16 + lrow8;
#pragma unroll
                for (int g = 0; g < 8; ++g) {
                    const int jj = g * 2 + lk;
                    uint32_t voff = vrow * 256 + ((jj ^ (vrow & 7)) << 4);
                    uint32_t vh[4];
                    ldsm4t(vh, sVh + voff);
                    mma16816(o[2 * g],     ap, vh[0], vh[1]);
                    mma16816(o[2 * g + 1], ap, vh[2], vh[3]);
                }
            }
        }

        __syncthreads();
        if (kt + 2 <= ktmax) load_kv(kt & 1, (kt + 2) << 6);
        CP_COMMIT();
    }

    const float inv0 = 1.0f / l_i[0];
    const float inv1 = 1.0f / l_i[1];
    const size_t ybase = (size_t)b * Sdim * Cdim + (size_t)h * Ddim;
    __half* yh = g_yh + ybase;
    const size_t row0 = (size_t)(m0 + wm + gid) * Cdim;
    const size_t row1 = row0 + 8 * Cdim;
#pragma unroll
    for (int nt = 0; nt < 16; ++nt) {
        const int col = nt * 8 + tig * 2;
        *(uint32_t*)(yh + row0 + col) = pack_f16(o[nt][0] * inv0, o[nt][1] * inv0);
        *(uint32_t*)(yh + row1 + col) = pack_f16(o[nt][2] * inv1, o[nt][3] * inv1);
    }
}

// ---------------------------------------------------------------------------
// Launch
// ---------------------------------------------------------------------------
extern "C" void kernel_launch(void* const* d_in, const int* in_sizes, int n_in,
                              void* d_out, int out_size)
{
    const float* x      = (const float*)d_in[0];
    const float* w_qkv  = (const float*)d_in[1];
    const float* b_qkv  = (const float*)d_in[2];
    const float* w_proj = (const float*)d_in[3];
    const float* b_proj = (const float*)d_in[4];
    float* out = (float*)d_out;

    __half *qkvh, *xh, *yh, *wq, *wp;
    cudaGetSymbolAddress((void**)&qkvh, g_qkvh);
    cudaGetSymbolAddress((void**)&xh,  g_xh);
    cudaGetSymbolAddress((void**)&yh,  g_yh);
    cudaGetSymbolAddress((void**)&wq,  g_wqkvT);
    cudaGetSymbolAddress((void**)&wp,  g_wprojT);

    cudaFuncSetAttribute(gemm_mma_kernel<0>,
                         cudaFuncAttributeMaxDynamicSharedMemorySize, GEMM_SMEM);
    cudaFuncSetAttribute(gemm_mma_kernel<1>,
                         cudaFuncAttributeMaxDynamicSharedMemorySize, GEMM_SMEM);
    cudaFuncSetAttribute(attn_mma_kernel,
                         cudaFuncAttributeMaxDynamicSharedMemorySize, ATTN_SMEM);

    // 1) fused prologue: x convert + both weight transposes (one launch)
    prologue_kernel<<<NB_PRO, 256>>>(x, xh, w_qkv, wq, w_proj, wp);

    // 2) qkv = x @ w_qkv + b_qkv   [8192, 6144] -> fp16
    gemm_mma_kernel<1><<<dim3(QKV_N / 128, Mtok / 128), 256, GEMM_SMEM>>>(
        xh, wq, b_qkv, nullptr, qkvh, Mtok, QKV_N, Cdim);

    // 3) flash attention (fp16) -> yh  (LPT block order)
    {
        dim3 grid(Sdim / 128, Hdim, Bdim);
        attn_mma_kernel<<<grid, 256, ATTN_SMEM>>>();
    }

    // 4) out = y @ w_proj + b_proj   [8192, 2048] fp32
    gemm_mma_kernel<0><<<dim3(Cdim / 128, Mtok / 128), 256, GEMM_SMEM>>>(
        yh, wp, b_proj, out, nullptr, Mtok, Cdim, Cdim);
}

// round 17
// speedup vs baseline: 1.0080x; 1.0013x over previous
#include <cuda_runtime.h>
#include <cuda_fp16.h>
#include <cstdint>

// Problem constants
#define Cdim 2048
#define Sdim 2048
#define Bdim 4
#define Hdim 16
#define Ddim 128
#define Mtok (Bdim * Sdim)          // 8192
#define QKV_N (3 * Cdim)            // 6144

// ---------------------------------------------------------------------------
// Scratch (device globals — no allocation allowed)
// ---------------------------------------------------------------------------
__device__ __half g_qkvh[(size_t)Mtok * QKV_N];      // qkv (fp16)
__device__ __half g_xh[(size_t)Mtok * Cdim];         // x   (fp16)
__device__ __half g_yh[(size_t)Mtok * Cdim];         // y   (fp16)
__device__ __half g_wqkvT[(size_t)QKV_N * Cdim];     // [6144, 2048] (N,K) fp16
__device__ __half g_wprojT[(size_t)Cdim * Cdim];     // [2048, 2048] fp16

// ---------------------------------------------------------------------------
// PTX helpers (base-ISA only: cp.async / ldmatrix / mma.sync)
// ---------------------------------------------------------------------------
__device__ __forceinline__ uint32_t smem_u32(const void* p) {
    uint32_t a;
    asm("{ .reg .u64 t; cvta.to.shared.u64 t, %1; cvt.u32.u64 %0, t; }" : "=r"(a) : "l"(p));
    return a;
}

#define CP_ASYNC16(dst, src) \
    asm volatile("cp.async.cg.shared.global [%0], [%1], 16;" :: "r"(dst), "l"(src))
#define CP_COMMIT() asm volatile("cp.async.commit_group;" ::: "memory")
#define CP_WAIT(n)  asm volatile("cp.async.wait_group %0;" :: "n"(n) : "memory")

__device__ __forceinline__ void ldsm4(uint32_t* r, uint32_t addr) {
    asm volatile("ldmatrix.sync.aligned.m8n8.x4.shared.b16 {%0,%1,%2,%3}, [%4];"
                 : "=r"(r[0]), "=r"(r[1]), "=r"(r[2]), "=r"(r[3]) : "r"(addr));
}
__device__ __forceinline__ void ldsm4t(uint32_t* r, uint32_t addr) {
    asm volatile("ldmatrix.sync.aligned.m8n8.x4.trans.shared.b16 {%0,%1,%2,%3}, [%4];"
                 : "=r"(r[0]), "=r"(r[1]), "=r"(r[2]), "=r"(r[3]) : "r"(addr));
}

// fp16 MMA, fp32 accumulate
__device__ __forceinline__ void mma16816(float* d, const uint32_t* a,
                                         uint32_t b0, uint32_t b1) {
    asm volatile(
        "mma.sync.aligned.m16n8k16.row.col.f32.f16.f16.f32 "
        "{%0,%1,%2,%3}, {%4,%5,%6,%7}, {%8,%9}, {%0,%1,%2,%3};"
        : "+f"(d[0]), "+f"(d[1]), "+f"(d[2]), "+f"(d[3])
        : "r"(a[0]), "r"(a[1]), "r"(a[2]), "r"(a[3]), "r"(b0), "r"(b1));
}

// pack two fp32 -> fp16x2 (first arg in low half)
__device__ __forceinline__ uint32_t pack_f16(float lo, float hi) {
    uint32_t r;
    asm("cvt.rn.f16x2.f32 %0, %1, %2;" : "=r"(r) : "f"(hi), "f"(lo));
    return r;
}

// ---------------------------------------------------------------------------
// Prologue kernels.
// Main (critical path): x convert + w_qkv transpose, one launch.
// Side (overlaps QKV GEMM): w_proj transpose (consumed only by kernel 4).
// ---------------------------------------------------------------------------
#define NB_CONV (Mtok * Cdim / 8 / 256)          // 8192
#define NB_TQ   ((QKV_N / 128) * (Cdim / 32))    // 3072
#define NB_TP   ((Cdim / 128) * (Cdim / 32))     // 1024
#define NB_MAIN (NB_CONV + NB_TQ)                // 11264

__device__ __forceinline__ void transpose_tile(const float* __restrict__ W,
                                               __half* __restrict__ Th,
                                               int K, int N, int bx, int by,
                                               float (*tile)[129])
{
    const int n0 = bx * 128, k0 = by * 32;
    const int t = threadIdx.x;   // 0..255

#pragma unroll
    for (int i = 0; i < 4; ++i) {
        int idx = t + i * 256;           // 0..1023
        int row = idx >> 5;              // k-row 0..31
        int col = (idx & 31) * 4;        // n-col 0..124
        float4 v = *(const float4*)(W + (size_t)(k0 + row) * N + n0 + col);
        tile[row][col + 0] = v.x;
        tile[row][col + 1] = v.y;
        tile[row][col + 2] = v.z;
        tile[row][col + 3] = v.w;
    }
    __syncthreads();

#pragma unroll
    for (int i = 0; i < 4; ++i) {
        int idx  = t + i * 256;          // 0..1023
        int nrow = idx >> 3;             // 0..127
        int kcol = (idx & 7) * 4;        // 0..28
        uint2 o;
        o.x = pack_f16(tile[kcol + 0][nrow], tile[kcol + 1][nrow]);
        o.y = pack_f16(tile[kcol + 2][nrow], tile[kcol + 3][nrow]);
        *(uint2*)(Th + (size_t)(n0 + nrow) * K + k0 + kcol) = o;
    }
}

__global__ __launch_bounds__(256) void prologue_main_kernel(
    const float* __restrict__ x,      __half* __restrict__ xh,
    const float* __restrict__ w_qkv,  __half* __restrict__ wqT)
{
    __shared__ float tile[32][129];
    const int bid = blockIdx.x;

    if (bid < NB_CONV) {
        int i = (bid * 256 + threadIdx.x) * 8;
        float4 a = *(const float4*)(x + i);
        float4 b = *(const float4*)(x + i + 4);
        uint4 o;
        o.x = pack_f16(a.x, a.y);
        o.y = pack_f16(a.z, a.w);
        o.z = pack_f16(b.x, b.y);
        o.w = pack_f16(b.z, b.w);
        *(uint4*)(xh + i) = o;
    } else {
        int tb = bid - NB_CONV;
        transpose_tile(w_qkv, wqT, Cdim, QKV_N, tb % (QKV_N / 128), tb / (QKV_N / 128), tile);
    }
}

__global__ __launch_bounds__(256) void prologue_wp_kernel(
    const float* __restrict__ w_proj, __half* __restrict__ wpT)
{
    __shared__ float tile[32][129];
    const int tb = blockIdx.x;
    transpose_tile(w_proj, wpT, Cdim, Cdim, tb % (Cdim / 128), tb / (Cdim / 128), tile);
}

// ---------------------------------------------------------------------------
// fp16 single-pass GEMM (R15/R16 body — best measured): C = A @ B^T + bias.
// CTA 128x128, BK=64, 8 warps (4m x 2n) 32x64 warp tiles, 3-stage cp.async,
// 2 CTAs/SM. ldsm addresses precomputed; k16 stepped by XOR (k16<<5).
// OUTM=0: fp32 C.  OUTM=1: fp16 Ch.
// ---------------------------------------------------------------------------
#define GA_TILE 16384                      // 128 x 64 fp16
#define GSTAGE (2 * GA_TILE)               // A, B = 32768
#define GEMM_SMEM (3 * GSTAGE)             // 98304

template<int OUTM>
__global__ __launch_bounds__(256, 2) void gemm_mma_kernel(
    const __half* __restrict__ Ah,
    const __half* __restrict__ Bh,
    const float* __restrict__ bias, float* __restrict__ C,
    __half* __restrict__ Ch,
    int M, int N, int K)
{
    extern __shared__ char smem[];
    const uint32_t sbase = smem_u32(smem);

    const int t   = threadIdx.x;
    const int wid = t >> 5;
    const int lid = t & 31;
    const int n0  = blockIdx.x * 128;
    const int m0  = blockIdx.y * 128;
    const int wm  = (wid & 3) * 32;
    const int wn  = (wid >> 2) * 64;

    const __half* gA = Ah + (size_t)m0 * K;
    const __half* gB = Bh + (size_t)n0 * K;

    float acc[2][8][4];
#pragma unroll
    for (int mt = 0; mt < 2; ++mt)
#pragma unroll
        for (int nt = 0; nt < 8; ++nt)
#pragma unroll
            for (int e = 0; e < 4; ++e) acc[mt][nt][e] = 0.f;

    auto load_stage = [&](int stage, int k0) {
        uint32_t sb = sbase + stage * GSTAGE;
#pragma unroll
        for (int i = 0; i < 4; ++i) {
            int idx = t + i * 256;          // < 1024
            int row = idx >> 3, j = idx & 7;
            uint32_t dst = sb + row * 128 + ((j ^ (row & 7)) << 4);
            CP_ASYNC16(dst, gA + (size_t)row * K + k0 + j * 8);
            CP_ASYNC16(dst + GA_TILE, gB + (size_t)row * K + k0 + j * 8);
        }
    };

    const int lrow8 = (lid & 7) + ((lid >> 3) & 1) * 8;
    const int lk    = (lid >> 4) & 1;
    uint32_t aoff0[2], boff0[4];
#pragma unroll
    for (int mt = 0; mt < 2; ++mt) {
        int r = wm + mt * 16 + lrow8;
        aoff0[mt] = r * 128 + ((lk ^ (r & 7)) << 4);
    }
#pragma unroll
    for (int nb = 0; nb < 4; ++nb) {
        int r = wn + nb * 16 + lrow8;
        boff0[nb] = GA_TILE + r * 128 + ((lk ^ (r & 7)) << 4);
    }

    const int nk = K / 64;                  // 32 chunks
    load_stage(0, 0);  CP_COMMIT();
    load_stage(1, 64); CP_COMMIT();

    for (int c = 0; c < nk; ++c) {
        CP_WAIT(1);
        __syncthreads();
        if (c + 2 < nk) load_stage((c + 2) % 3, (c + 2) * 64);
        CP_COMMIT();

        const uint32_t sb = sbase + (c % 3) * GSTAGE;

#pragma unroll
        for (int k16 = 0; k16 < 4; ++k16) {
            const uint32_t x = (uint32_t)k16 << 5;

            uint32_t bh[16];
#pragma unroll
            for (int nb = 0; nb < 4; ++nb)
                ldsm4(&bh[nb * 4], (sb + boff0[nb]) ^ x);
#pragma unroll
            for (int mt = 0; mt < 2; ++mt) {
                uint32_t ah[4];
                ldsm4(ah, (sb + aoff0[mt]) ^ x);
#pragma unroll
                for (int nb = 0; nb < 4; ++nb) {
                    mma16816(acc[mt][2 * nb],     ah, bh[nb * 4 + 0], bh[nb * 4 + 2]);
                    mma16816(acc[mt][2 * nb + 1], ah, bh[nb * 4 + 1], bh[nb * 4 + 3]);
                }
            }
        }
    }

    const int gid = lid >> 2;
    const int tig = lid & 3;
#pragma unroll
    for (int mt = 0; mt < 2; ++mt) {
        int m = m0 + wm + mt * 16 + gid;
#pragma unroll
        for (int nt = 0; nt < 8; ++nt) {
            int n = n0 + wn + nt * 8 + tig * 2;
            float b0 = bias[n], b1 = bias[n + 1];
            float v00 = acc[mt][nt][0] + b0, v01 = acc[mt][nt][1] + b1;
            float v10 = acc[mt][nt][2] + b0, v11 = acc[mt][nt][3] + b1;
            if (OUTM == 0) {
                *(float2*)(C + (size_t)m * N + n)       = make_float2(v00, v01);
                *(float2*)(C + (size_t)(m + 8) * N + n) = make_float2(v10, v11);
            } else {
                *(uint32_t*)(Ch + (size_t)m * N + n)       = pack_f16(v00, v01);
                *(uint32_t*)(Ch + (size_t)(m + 8) * N + n) = pack_f16(v10, v11);
            }
        }
    }
}

// ---------------------------------------------------------------------------
// Flash attention, pure fp16 MMA operands, causal. (R13 config — unchanged)
// CTA: 128 q-rows x 64-kv chunks. 8 warps x 16 q-rows. 2-stage KV, 2 CTAs/SM.
// LPT scheduling: heaviest q-tiles (largest qt) launch first.
// ---------------------------------------------------------------------------
#define KV_TILE_B 16384                     // 64 rows x 256 B
#define KV_STAGE_B (2 * KV_TILE_B)          // K, V
#define Q_TILE_B   32768                    // 128 rows x 256 B
#define ATTN_SMEM (Q_TILE_B + 2 * KV_STAGE_B)   // 98304

__global__ __launch_bounds__(256, 2) void attn_mma_kernel()
{
    extern __shared__ char sm8[];
    const uint32_t sb  = smem_u32(sm8);
    const uint32_t sQh = sb;
    const uint32_t sKV = sb + Q_TILE_B;

    const int t   = threadIdx.x;
    const int wid = t >> 5;
    const int lid = t & 31;
    const int qt  = (Sdim / 128 - 1) - blockIdx.x;   // LPT: heavy tiles first
    const int h   = blockIdx.y;
    const int b   = blockIdx.z;
    const int m0  = qt * 128;
    const int wm  = wid * 16;
    const int gid = lid >> 2;
    const int tig = lid & 3;
    const int lrow8 = (lid & 7) + ((lid >> 3) & 1) * 8;
    const int lk    = (lid >> 4) & 1;

    const size_t tok0 = ((size_t)b * Sdim + m0) * QKV_N;
    const __half* qh = g_qkvh + tok0 + h * Ddim;
    const size_t kvtok = (size_t)b * Sdim * QKV_N;
    const __half* kv_base[2] = {
        g_qkvh + kvtok + Cdim + h * Ddim,      // K
        g_qkvh + kvtok + 2 * Cdim + h * Ddim   // V
    };

    auto load_kv = [&](int stage, int n0) {
        uint32_t dstb = sKV + stage * KV_STAGE_B;
#pragma unroll
        for (int i = 0; i < 8; ++i) {
            int idx  = t + i * 256;            // 0..2047
            int tile = idx >> 10;
            int rem  = idx & 1023;
            int row  = rem >> 4, j = rem & 15;
            const void* src = kv_base[tile] + (size_t)(n0 + row) * QKV_N + j * 8;
            uint32_t dst = dstb + tile * KV_TILE_B + row * 256 + ((j ^ (row & 7)) << 4);
            CP_ASYNC16(dst, src);
        }
    };

    const int ktmax = (m0 >> 6) + 1;

#pragma unroll
    for (int i = 0; i < 8; ++i) {
        int idx  = t + i * 256;                // 0..2047
        int row  = idx >> 4, j = idx & 15;
        const __half* src = qh + (size_t)row * QKV_N + j * 8;
        uint32_t dst = sQh + row * 256 + ((j ^ (row & 7)) << 4);
        CP_ASYNC16(dst, src);
    }
    load_kv(0, 0);
    CP_COMMIT();                               // g0: Q + kv0
    if (ktmax >= 1) load_kv(1, 64);
    CP_COMMIT();

    float o[16][4];
    float m_i[2] = {-1e30f, -1e30f};
    float l_i[2] = {0.f, 0.f};
#pragma unroll
    for (int nt = 0; nt < 16; ++nt)
#pragma unroll
        for (int e = 0; e < 4; ++e) o[nt][e] = 0.f;

    const float scale = 0.08838834764831845f;   // 1/sqrt(128)
    const int r0g = m0 + wm + gid;

    for (int kt = 0; kt <= ktmax; ++kt) {
        const int n0 = kt << 6;
        CP_WAIT(1);
        __syncthreads();

        const uint32_t st  = sKV + (kt & 1) * KV_STAGE_B;
        const uint32_t sKh = st, sVh = st + KV_TILE_B;

        if (m0 + wm + 15 >= n0) {
            // ---- S = Q K^T ----
            float s[8][4];
#pragma unroll
            for (int nt = 0; nt < 8; ++nt)
#pragma unroll
                for (int e = 0; e < 4; ++e) s[nt][e] = 0.f;

#pragma unroll
            for (int ks = 0; ks < 8; ++ks) {
                const int jg = ks * 2 + lk;
                const int arow = wm + lrow8;
                uint32_t aoff = arow * 256 + ((jg ^ (arow & 7)) << 4);
                uint32_t qf[4];
                ldsm4(qf, sQh + aoff);
#pragma unroll
                for (int g = 0; g < 4; ++g) {
                    const int brow = g * 16 + lrow8;
                    uint32_t boff = brow * 256 + ((jg ^ (brow & 7)) << 4);
                    uint32_t kh[4];
                    ldsm4(kh, sKh + boff);
                    mma16816(s[2 * g],     qf, kh[0], kh[2]);
                    mma16816(s[2 * g + 1], qf, kh[1], kh[3]);
                }
            }

            const bool diag = (n0 + 63 > m0 + wm);
#pragma unroll
            for (int nt = 0; nt < 8; ++nt) {
                const int c0 = n0 + nt * 8 + tig * 2;
#pragma unroll
                for (int e = 0; e < 4; ++e) s[nt][e] *= scale;
                if (diag) {
                    if (c0     > r0g)     s[nt][0] = -1e30f;
                    if (c0 + 1 > r0g)     s[nt][1] = -1e30f;
                    if (c0     > r0g + 8) s[nt][2] = -1e30f;
                    if (c0 + 1 > r0g + 8) s[nt][3] = -1e30f;
                }
            }

#pragma unroll
            for (int rr = 0; rr < 2; ++rr) {
                float mx = -1e30f;
#pragma unroll
                for (int nt = 0; nt < 8; ++nt)
                    mx = fmaxf(mx, fmaxf(s[nt][2 * rr], s[nt][2 * rr + 1]));
                mx = fmaxf(mx, __shfl_xor_sync(0xffffffffu, mx, 1));
                mx = fmaxf(mx, __shfl_xor_sync(0xffffffffu, mx, 2));
                float m_new = fmaxf(m_i[rr], mx);
                float alpha = __expf(m_i[rr] - m_new);
                float sum = 0.f;
#pragma unroll
                for (int nt = 0; nt < 8; ++nt) {
                    float p0 = __expf(s[nt][2 * rr]     - m_new);
                    float p1 = __expf(s[nt][2 * rr + 1] - m_new);
                    s[nt][2 * rr]     = p0;
                    s[nt][2 * rr + 1] = p1;
                    sum += p0 + p1;
                }
                sum += __shfl_xor_sync(0xffffffffu, sum, 1);
                sum += __shfl_xor_sync(0xffffffffu, sum, 2);
                l_i[rr] = l_i[rr] * alpha + sum;
                m_i[rr] = m_new;
#pragma unroll
                for (int nt = 0; nt < 16; ++nt) {
                    o[nt][2 * rr]     *= alpha;
                    o[nt][2 * rr + 1] *= alpha;
                }
            }

#pragma unroll
            for (int j = 0; j < 4; ++j) {
                uint32_t ap[4];
#pragma unroll
                for (int half = 0; half < 2; ++half) {
                    const float* sp = s[2 * j + half];
                    ap[half * 2 + 0] = pack_f16(sp[0], sp[1]);
                    ap[half * 2 + 1] = pack_f16(sp[2], sp[3]);
                }
                const int vrow = j * 16 + lrow8;
#pragma unroll
                for (int g = 0; g < 8; ++g) {
                    const int jj = g * 2 + lk;
                    uint32_t voff = vrow * 256 + ((jj ^ (vrow & 7)) << 4);
                    uint32_t vh[4];
                    ldsm4t(vh, sVh + voff);
                    mma16816(o[2 * g],     ap, vh[0], vh[1]);
                    mma16816(o[2 * g + 1], ap, vh[2], vh[3]);
                }
            }
        }

        __syncthreads();
        if (kt + 2 <= ktmax) load_kv(kt & 1, (kt + 2) << 6);
        CP_COMMIT();
    }

    const float inv0 = 1.0f / l_i[0];
    const float inv1 = 1.0f / l_i[1];
    const size_t ybase = (size_t)b * Sdim * Cdim + (size_t)h * Ddim;
    __half* yh = g_yh + ybase;
    const size_t row0 = (size_t)(m0 + wm + gid) * Cdim;
    const size_t row1 = row0 + 8 * Cdim;
#pragma unroll
    for (int nt = 0; nt < 16; ++nt) {
        const int col = nt * 8 + tig * 2;
        *(uint32_t*)(yh + row0 + col) = pack_f16(o[nt][0] * inv0, o[nt][1] * inv0);
        *(uint32_t*)(yh + row1 + col) = pack_f16(o[nt][2] * inv1, o[nt][3] * inv1);
    }
}

// ---------------------------------------------------------------------------
// Launch: wp transpose forked to a side stream (consumed only by kernel 4),
// overlapping with the QKV GEMM. Standard capture-safe fork/join via events.
// ---------------------------------------------------------------------------
extern "C" void kernel_launch(void* const* d_in, const int* in_sizes, int n_in,
                              void* d_out, int out_size)
{
    const float* x      = (const float*)d_in[0];
    const float* w_qkv  = (const float*)d_in[1];
    const float* b_qkv  = (const float*)d_in[2];
    const float* w_proj = (const float*)d_in[3];
    const float* b_proj = (const float*)d_in[4];
    float* out = (float*)d_out;

    __half *qkvh, *xh, *yh, *wq, *wp;
    cudaGetSymbolAddress((void**)&qkvh, g_qkvh);
    cudaGetSymbolAddress((void**)&xh,  g_xh);
    cudaGetSymbolAddress((void**)&yh,  g_yh);
    cudaGetSymbolAddress((void**)&wq,  g_wqkvT);
    cudaGetSymbolAddress((void**)&wp,  g_wprojT);

    cudaFuncSetAttribute(gemm_mma_kernel<0>,
                         cudaFuncAttributeMaxDynamicSharedMemorySize, GEMM_SMEM);
    cudaFuncSetAttribute(gemm_mma_kernel<1>,
                         cudaFuncAttributeMaxDynamicSharedMemorySize, GEMM_SMEM);
    cudaFuncSetAttribute(attn_mma_kernel,
                         cudaFuncAttributeMaxDynamicSharedMemorySize, ATTN_SMEM);

    // Side stream + fork/join events (host resources only; no device memory)
    cudaStream_t s2;
    cudaEvent_t evFork, evJoin;
    cudaStreamCreateWithFlags(&s2, cudaStreamNonBlocking);
    cudaEventCreateWithFlags(&evFork, cudaEventDisableTiming);
    cudaEventCreateWithFlags(&evJoin, cudaEventDisableTiming);

    // Fork: wp transpose on side stream (needed only by the final proj GEMM)
    cudaEventRecord(evFork, 0);
    cudaStreamWaitEvent(s2, evFork, 0);
    prologue_wp_kernel<<<NB_TP, 256, 0, s2>>>(w_proj, wp);
    cudaEventRecord(evJoin, s2);

    // 1) critical-path prologue: x convert + w_qkv transpose
    prologue_main_kernel<<<NB_MAIN, 256>>>(x, xh, w_qkv, wq);

    // 2) qkv = x @ w_qkv + b_qkv   [8192, 6144] -> fp16
    gemm_mma_kernel<1><<<dim3(QKV_N / 128, Mtok / 128), 256, GEMM_SMEM>>>(
        xh, wq, b_qkv, nullptr, qkvh, Mtok, QKV_N, Cdim);

    // 3) flash attention (fp16) -> yh  (LPT block order)
    {
        dim3 grid(Sdim / 128, Hdim, Bdim);
        attn_mma_kernel<<<grid, 256, ATTN_SMEM>>>();
    }

    // Join: wp must be ready before proj GEMM
    cudaStreamWaitEvent(0, evJoin, 0);

    // 4) out = y @ w_proj + b_proj   [8192, 2048] fp32
    gemm_mma_kernel<0><<<dim3(Cdim / 128, Mtok / 128), 256, GEMM_SMEM>>>(
        yh, wp, b_proj, out, nullptr, Mtok, Cdim, Cdim);
}